// round 14
// baseline (speedup 1.0000x reference)
#include <cuda_runtime.h>
#include <cuda_bf16.h>
#include <cstdint>

#define N_V 4096
#define N_E 8192
#define HD  128
#define ATOM_DIM 64
#define BOND_DIM 32
#define N_LAYER 4

#define PB 128                    // persistent blocks = vertex partitions
#define PT 512                    // 16 warps
#define NWARP_P (PB * 16)
#define MAXE 24                   // max edges per src row

// ---------------------------------------------------------------------------
// Scratch
// ---------------------------------------------------------------------------
__device__ float g_tmpv[N_V * HD];
__device__ float g_tmpe[N_E * HD];
__device__ float g_he  [N_E * HD];
__device__ float g_hvA [N_V * HD];
__device__ int   g_src [N_E];
__device__ int   g_dst [N_E];
__device__ unsigned g_count = 0;
__device__ volatile unsigned g_sense = 0;

// ---------------------------------------------------------------------------
// f32x2 packed helpers
// ---------------------------------------------------------------------------
__device__ __forceinline__ unsigned long long pack2(float a, float b) {
    unsigned long long r;
    asm("mov.b64 %0, {%1, %2};" : "=l"(r) : "f"(a), "f"(b));
    return r;
}
__device__ __forceinline__ void fma2(unsigned long long& d,
                                     unsigned long long a, unsigned long long b) {
    asm("fma.rn.f32x2 %0, %1, %2, %0;" : "+l"(d) : "l"(a), "l"(b));
}
__device__ __forceinline__ float2 unpack2(unsigned long long v) {
    float2 r;
    asm("mov.b64 {%0, %1}, %2;" : "=f"(r.x), "=f"(r.y) : "l"(v));
    return r;
}
__device__ __forceinline__ float lrelu(float v) { return v > 0.0f ? v : 0.01f * v; }

// ---------------------------------------------------------------------------
// Grid barrier (PB blocks, 1/SM). gpu-scope fence is load-bearing.
// ---------------------------------------------------------------------------
__device__ __forceinline__ void gsync() {
    __syncthreads();
    if (threadIdx.x == 0) {
        __threadfence();
        unsigned gen = g_sense;
        if (atomicAdd(&g_count, 1u) == PB - 1u) {
            g_count = 0;
            __threadfence();
            g_sense = gen + 1u;
        } else {
            while (g_sense == gen) { }
        }
    }
    __syncthreads();
}

// ---------------------------------------------------------------------------
// One-hot scan — cp.async (LDGSTS) double-buffered pipeline.
// Data lands in smem, so in-flight bytes are decoupled from the register
// file: 2 x 32 KB per block in flight vs 4 KB with register LDGs.
// ---------------------------------------------------------------------------
__device__ __forceinline__ void proc_f4(float4 v, int p, int* __restrict__ outp)
{
    if (v.x != 0.0f || v.y != 0.0f || v.z != 0.0f || v.w != 0.0f) {
        int lin = p << 2;
        int row = lin >> 13;
        int col = lin & (N_E - 1);
        if (v.x != 0.0f) outp[col + 0] = row;
        if (v.y != 0.0f) outp[col + 1] = row;
        if (v.z != 0.0f) outp[col + 2] = row;
        if (v.w != 0.0f) outp[col + 3] = row;
    }
}

#define XB_BLOCKS 1024

__device__ void extract_body(const float* __restrict__ mat,
                             int* __restrict__ outp, int xb, char* sbuf)
{
    const int PER = N_V * (N_E / 4);      // 8,388,608 float4 per matrix
    const int T   = XB_BLOCKS * 256;      // 262,144 threads
    const int tid = threadIdx.x;
    const int base = xb * 256 + tid;      // 32 float4 per thread = 4 batches of 8
    const float4* m4 = reinterpret_cast<const float4*>(mat);
    const float4* sb = reinterpret_cast<const float4*>(sbuf);

    unsigned int sbase;
    asm("{ .reg .u64 t; cvta.to.shared.u64 t, %1; cvt.u32.u64 %0, t; }"
        : "=r"(sbase) : "l"(sbuf));

    // prologue: issue batch 0 into buffer 0
#pragma unroll
    for (int u = 0; u < 8; u++) {
        unsigned int sa = sbase + (u * 256 + tid) * 16;
        const float4* ga = &m4[base + u * T];
        asm volatile("cp.async.cg.shared.global [%0], [%1], 16;" :: "r"(sa), "l"(ga));
    }
    asm volatile("cp.async.commit_group;");

#pragma unroll
    for (int b = 0; b < 4; b++) {
        if (b + 1 < 4) {
            int buf = (b + 1) & 1;
#pragma unroll
            for (int u = 0; u < 8; u++) {
                unsigned int sa = sbase + (buf * 2048 + u * 256 + tid) * 16;
                const float4* ga = &m4[base + ((b + 1) * 8 + u) * T];
                asm volatile("cp.async.cg.shared.global [%0], [%1], 16;" :: "r"(sa), "l"(ga));
            }
            asm volatile("cp.async.commit_group;");
            asm volatile("cp.async.wait_group 1;");   // batch b landed
        } else {
            asm volatile("cp.async.wait_group 0;");
        }
        int buf = b & 1;
#pragma unroll
        for (int u = 0; u < 8; u++) {
            float4 v = sb[buf * 2048 + u * 256 + tid];
            proc_f4(v, base + (b * 8 + u) * T, outp);
        }
    }
}

// ---------------------------------------------------------------------------
// Register-tiled GEMM body (rides under the scans): f32x2 inner product.
// C[64,128] = act(A[64,K] @ W[128,K]^T + b); ACT 0=leaky, 1=tanh
// Optional C3 (pitch 384, offset 2*HD: he_out segment 2).
// ---------------------------------------------------------------------------
template<int K, int ACT>
__device__ __forceinline__ void gemm_body(const float* __restrict__ A,
                                          const float* __restrict__ W,
                                          const float* __restrict__ bias,
                                          float* __restrict__ C,
                                          float* __restrict__ C3,
                                          int m0, float* sA, float* sW)
{
    constexpr int BM = 64, BK = 16, BN = 128;
    const int tid = threadIdx.x;
    const int tx  = tid & 15;
    const int ty  = tid >> 4;

    unsigned long long acc[4][4];
#pragma unroll
    for (int i = 0; i < 4; i++)
#pragma unroll
        for (int j = 0; j < 4; j++) acc[i][j] = 0ull;

#pragma unroll
    for (int k0 = 0; k0 < K; k0 += BK) {
        {
            int j0 = tid * 4, m = j0 >> 4, k = j0 & 15;
            float4 a4 = *reinterpret_cast<const float4*>(&A[(m0 + m) * K + k0 + k]);
            sA[(k + 0) * BM + m] = a4.x; sA[(k + 1) * BM + m] = a4.y;
            sA[(k + 2) * BM + m] = a4.z; sA[(k + 3) * BM + m] = a4.w;
        }
        {
            int j0 = tid * 8, n = j0 >> 4, kk = j0 & 15;
            const float* wr = &W[n * K + k0 + kk];
            float4 w0 = *reinterpret_cast<const float4*>(wr);
            float4 w1 = *reinterpret_cast<const float4*>(wr + 4);
            sW[(kk + 0) * BN + n] = w0.x; sW[(kk + 1) * BN + n] = w0.y;
            sW[(kk + 2) * BN + n] = w0.z; sW[(kk + 3) * BN + n] = w0.w;
            sW[(kk + 4) * BN + n] = w1.x; sW[(kk + 5) * BN + n] = w1.y;
            sW[(kk + 6) * BN + n] = w1.z; sW[(kk + 7) * BN + n] = w1.w;
        }
        __syncthreads();
#pragma unroll
        for (int k = 0; k < BK; k++) {
            float a[4];
#pragma unroll
            for (int i = 0; i < 4; i++) a[i] = sA[k * BM + ty * 4 + i];
            ulonglong2 w01 = *reinterpret_cast<const ulonglong2*>(&sW[k * BN + tx * 8]);
            ulonglong2 w23 = *reinterpret_cast<const ulonglong2*>(&sW[k * BN + tx * 8 + 4]);
#pragma unroll
            for (int i = 0; i < 4; i++) {
                unsigned long long aa = pack2(a[i], a[i]);
                fma2(acc[i][0], aa, w01.x);
                fma2(acc[i][1], aa, w01.y);
                fma2(acc[i][2], aa, w23.x);
                fma2(acc[i][3], aa, w23.y);
            }
        }
        __syncthreads();
    }

    float b[8];
#pragma unroll
    for (int j = 0; j < 8; j++) b[j] = bias[tx * 8 + j];

#pragma unroll
    for (int i = 0; i < 4; i++) {
        int m = m0 + ty * 4 + i;
        float out[8];
#pragma unroll
        for (int j = 0; j < 4; j++) {
            float2 v = unpack2(acc[i][j]);
            float u0 = v.x + b[j * 2];
            float u1 = v.y + b[j * 2 + 1];
            if (ACT == 0) { u0 = lrelu(u0); u1 = lrelu(u1); }
            else          { u0 = tanhf(u0); u1 = tanhf(u1); }
            out[j * 2]     = u0;
            out[j * 2 + 1] = u1;
        }
        float4 o0 = make_float4(out[0], out[1], out[2], out[3]);
        float4 o1 = make_float4(out[4], out[5], out[6], out[7]);
        float* crow = &C[m * HD + tx * 8];
        *reinterpret_cast<float4*>(crow)     = o0;
        *reinterpret_cast<float4*>(crow + 4) = o1;
        if (C3) {
            float* c3row = &C3[m * (3 * HD) + 2 * HD + tx * 8];
            *reinterpret_cast<float4*>(c3row)     = o0;
            *reinterpret_cast<float4*>(c3row + 4) = o1;
        }
    }
}

// K1: stage-1 linears + vew1 scan (src). 64 KB dynamic smem (scan buffers;
// GEMM branch uses the first 12 KB as sA/sW).
__global__ __launch_bounds__(256)
void k1_kernel(const float* __restrict__ atom, const float* __restrict__ bond,
               const float* __restrict__ vW1, const float* __restrict__ vb1,
               const float* __restrict__ eW1, const float* __restrict__ eb1,
               const float* __restrict__ vew1,
               float* __restrict__ tmpv, float* __restrict__ tmpe,
               int* __restrict__ src)
{
    extern __shared__ char sbuf[];
    float* sA = reinterpret_cast<float*>(sbuf);
    float* sW = sA + 16 * 64;
    int b = blockIdx.x;
    if (b < 64)
        gemm_body<ATOM_DIM, 0>(atom, vW1, vb1, tmpv, nullptr, b * 64, sA, sW);
    else if (b < 192)
        gemm_body<BOND_DIM, 0>(bond, eW1, eb1, tmpe, nullptr, (b - 64) * 64, sA, sW);
    else
        extract_body(vew1, src, b - 192, sbuf);
}

// K2: stage-2 linears (tanh; e-branch also writes he_out seg2) + vew2 scan (dst)
__global__ __launch_bounds__(256)
void k2_kernel(const float* __restrict__ tmpv, const float* __restrict__ tmpe,
               const float* __restrict__ vW2, const float* __restrict__ vb2,
               const float* __restrict__ eW2, const float* __restrict__ eb2,
               const float* __restrict__ vew2,
               float* __restrict__ hvA, float* __restrict__ he,
               float* __restrict__ he_out, int* __restrict__ dst)
{
    extern __shared__ char sbuf[];
    float* sA = reinterpret_cast<float*>(sbuf);
    float* sW = sA + 16 * 64;
    int b = blockIdx.x;
    if (b < 64)
        gemm_body<HD, 1>(tmpv, vW2, vb2, hvA, nullptr, b * 64, sA, sW);
    else if (b < 192)
        gemm_body<HD, 1>(tmpe, eW2, eb2, he, he_out, (b - 64) * 64, sA, sW);
    else
        extract_body(vew2, dst, b - 192, sbuf);
}

// ---------------------------------------------------------------------------
// Persistent kernel — byte-identical structure to R12 best (104.6us).
// ---------------------------------------------------------------------------
__global__ __launch_bounds__(PT, 1)
void persist_kernel(const float* __restrict__ he,
                    float* __restrict__ hvA,
                    const int* __restrict__ src, const int* __restrict__ dst,
                    const float* __restrict__ mlpW, const float* __restrict__ mlpb,
                    float* __restrict__ hv_out, float* __restrict__ he_out)
{
    extern __shared__ float smem[];
    float* sW   = smem;                       // 16384 floats
    float* sAcc = smem + 16384;               // 4096 floats
    int*   sList = (int*)(smem + 20480);      // 32 * MAXE ints
    int*   sCnt  = (int*)(smem + 20480 + 32 * MAXE);  // 32 ints

    const int tid  = threadIdx.x;
    const int wid  = tid >> 5;
    const int lane = tid & 31;
    const int bid  = blockIdx.x;
    const int m0   = bid * 32;

    const float4* he4 = reinterpret_cast<const float4*>(he);
    const float4* hv4 = reinterpret_cast<const float4*>(hvA);

    if (tid < 32) sCnt[tid] = 0;
    __syncthreads();
    for (int e = tid; e < N_E; e += PT) {
        int s = __ldg(&src[e]);
        if ((s >> 5) == bid) {
            int rr = s & 31;
            int slot = atomicAdd(&sCnt[rr], 1);
            if (slot < MAXE) sList[rr * MAXE + slot] = e;
        }
    }
    {
        float4* sAcc4 = reinterpret_cast<float4*>(sAcc);
        for (int idx = tid; idx < 1024; idx += PT)
            sAcc4[idx] = __ldg(&hv4[m0 * 32 + idx]);
    }
    __syncthreads();

    for (int l = 0; l < N_LAYER; l++) {
#pragma unroll
        for (int q = 0; q < 2; q++) {
            int rr = wid * 2 + q;
            int cnt = sCnt[rr]; if (cnt > MAXE) cnt = MAXE;
            float4 a = *reinterpret_cast<const float4*>(&sAcc[rr * HD + lane * 4]);
            for (int i = 0; i < cnt; i++) {
                int e = sList[rr * MAXE + i];
                int d = __ldg(&dst[e]);
                float4 h = __ldg(&he4[e * 32 + lane]);
                float4 g = __ldg(reinterpret_cast<const float4*>(hvA) + d * 32 + lane);
                a.x += fmaxf(h.x + g.x, 0.0f);
                a.y += fmaxf(h.y + g.y, 0.0f);
                a.z += fmaxf(h.z + g.z, 0.0f);
                a.w += fmaxf(h.w + g.w, 0.0f);
            }
            *reinterpret_cast<float4*>(&sAcc[rr * HD + lane * 4]) = a;
        }
        __syncthreads();

        const float* Wl = mlpW + l * (HD * HD);
        const float* bl = mlpb + l * HD;
        {
            int n  = tid & 127;
            int kq = (tid >> 7) * 32;
#pragma unroll
            for (int j = 0; j < 8; j++) {
                float4 w = __ldg(reinterpret_cast<const float4*>(&Wl[n * HD + kq + j * 4]));
                int k = kq + j * 4;
                sW[(k + 0) * HD + n] = w.x;
                sW[(k + 1) * HD + n] = w.y;
                sW[(k + 2) * HD + n] = w.z;
                sW[(k + 3) * HD + n] = w.w;
            }
        }
        __syncthreads();

        if (wid < 8) {
            const int r0 = wid * 4;
            const int c0 = lane * 4;
            unsigned long long acc[4][2];
#pragma unroll
            for (int r = 0; r < 4; r++) { acc[r][0] = 0ull; acc[r][1] = 0ull; }

            for (int k0 = 0; k0 < HD; k0 += 4) {
                float4 av[4];
#pragma unroll
                for (int r = 0; r < 4; r++)
                    av[r] = *reinterpret_cast<const float4*>(&sAcc[(r0 + r) * HD + k0]);
#pragma unroll
                for (int j = 0; j < 4; j++) {
                    ulonglong2 ww = *reinterpret_cast<const ulonglong2*>(&sW[(k0 + j) * HD + c0]);
#pragma unroll
                    for (int r = 0; r < 4; r++) {
                        float a = (j == 0) ? av[r].x : (j == 1) ? av[r].y
                                : (j == 2) ? av[r].z : av[r].w;
                        unsigned long long aa = pack2(a, a);
                        fma2(acc[r][0], aa, ww.x);
                        fma2(acc[r][1], aa, ww.y);
                    }
                }
            }

            float4 b4 = __ldg(reinterpret_cast<const float4*>(&bl[c0]));
            float4 o[4];
#pragma unroll
            for (int r = 0; r < 4; r++) {
                float2 v0 = unpack2(acc[r][0]);
                float2 v1 = unpack2(acc[r][1]);
                o[r] = make_float4(lrelu(v0.x + b4.x), lrelu(v0.y + b4.y),
                                   lrelu(v1.x + b4.z), lrelu(v1.y + b4.w));
            }
            __syncwarp();
#pragma unroll
            for (int r = 0; r < 4; r++) {
                int rr = r0 + r;
                *reinterpret_cast<float4*>(&sAcc[rr * HD + c0]) = o[r];
                *reinterpret_cast<float4*>(&hvA[(m0 + rr) * HD + c0]) = o[r];
                if (l == N_LAYER - 1)
                    *reinterpret_cast<float4*>(&hv_out[(m0 + rr) * HD + c0]) = o[r];
            }
        }
        gsync();
    }

    float4* out4 = reinterpret_cast<float4*>(he_out);
    for (int e = bid * 16 + wid; e < N_E; e += NWARP_P) {
        int s = __ldg(&src[e]);
        int d = __ldg(&dst[e]);
        out4[e * 96 + lane]      = __ldg(&hv4[s * 32 + lane]);
        out4[e * 96 + 32 + lane] = __ldg(&hv4[d * 32 + lane]);
    }
}

// ---------------------------------------------------------------------------
// Launcher
// ---------------------------------------------------------------------------
extern "C" void kernel_launch(void* const* d_in, const int* in_sizes, int n_in,
                              void* d_out, int out_size)
{
    const float* atom = (const float*)d_in[0];
    const float* bond = (const float*)d_in[1];
    const float* vew1 = (const float*)d_in[2];
    const float* vew2 = (const float*)d_in[3];
    const float* vW1  = (const float*)d_in[4];
    const float* vb1  = (const float*)d_in[5];
    const float* vW2  = (const float*)d_in[6];
    const float* vb2  = (const float*)d_in[7];
    const float* eW1  = (const float*)d_in[8];
    const float* eb1  = (const float*)d_in[9];
    const float* eW2  = (const float*)d_in[10];
    const float* eb2  = (const float*)d_in[11];
    const float* mlpW = (const float*)d_in[12];
    const float* mlpb = (const float*)d_in[13];

    float *tmpv, *tmpe, *he, *hvA;
    int *src, *dst;
    cudaGetSymbolAddress((void**)&tmpv, g_tmpv);
    cudaGetSymbolAddress((void**)&tmpe, g_tmpe);
    cudaGetSymbolAddress((void**)&he,   g_he);
    cudaGetSymbolAddress((void**)&hvA,  g_hvA);
    cudaGetSymbolAddress((void**)&src,  g_src);
    cudaGetSymbolAddress((void**)&dst,  g_dst);

    float* hv_out = (float*)d_out;
    float* he_out = (float*)d_out + (long long)N_V * HD;

    const int SCAN_SMEM = 65536;                                    // 64 KB
    const int PER_SMEM  = (16384 + 4096) * 4 + (32 * MAXE + 32) * 4;
    cudaFuncSetAttribute(k1_kernel,
                         cudaFuncAttributeMaxDynamicSharedMemorySize, SCAN_SMEM);
    cudaFuncSetAttribute(k2_kernel,
                         cudaFuncAttributeMaxDynamicSharedMemorySize, SCAN_SMEM);
    cudaFuncSetAttribute(persist_kernel,
                         cudaFuncAttributeMaxDynamicSharedMemorySize, PER_SMEM);

    k1_kernel<<<192 + XB_BLOCKS, 256, SCAN_SMEM>>>(atom, bond, vW1, vb1, eW1, eb1,
                                                   vew1, tmpv, tmpe, src);
    k2_kernel<<<192 + XB_BLOCKS, 256, SCAN_SMEM>>>(tmpv, tmpe, vW2, vb2, eW2, eb2,
                                                   vew2, hvA, he, he_out, dst);
    persist_kernel<<<PB, PT, PER_SMEM>>>(he, hvA, src, dst,
                                         mlpW, mlpb, hv_out, he_out);
}

// round 15
// speedup vs baseline: 1.1013x; 1.1013x over previous
#include <cuda_runtime.h>
#include <cuda_bf16.h>
#include <cstdint>

#define N_V 4096
#define N_E 8192
#define HD  128
#define ATOM_DIM 64
#define BOND_DIM 32
#define N_LAYER 4

#define PB 128                    // persistent blocks = vertex partitions
#define PT 512                    // 16 warps
#define NWARP_P (PB * 16)
#define MAXE 24                   // max edges per src row

// ---------------------------------------------------------------------------
// Scratch
// ---------------------------------------------------------------------------
__device__ float g_tmpv[N_V * HD];
__device__ float g_tmpe[N_E * HD];
__device__ float g_he  [N_E * HD];
__device__ float g_hvA [N_V * HD];
__device__ int   g_src [N_E];
__device__ int   g_dst [N_E];
__device__ unsigned g_count = 0;
__device__ volatile unsigned g_sense = 0;

// ---------------------------------------------------------------------------
// f32x2 packed helpers
// ---------------------------------------------------------------------------
__device__ __forceinline__ unsigned long long pack2(float a, float b) {
    unsigned long long r;
    asm("mov.b64 %0, {%1, %2};" : "=l"(r) : "f"(a), "f"(b));
    return r;
}
__device__ __forceinline__ void fma2(unsigned long long& d,
                                     unsigned long long a, unsigned long long b) {
    asm("fma.rn.f32x2 %0, %1, %2, %0;" : "+l"(d) : "l"(a), "l"(b));
}
__device__ __forceinline__ float2 unpack2(unsigned long long v) {
    float2 r;
    asm("mov.b64 {%0, %1}, %2;" : "=f"(r.x), "=f"(r.y) : "l"(v));
    return r;
}
__device__ __forceinline__ float lrelu(float v) { return v > 0.0f ? v : 0.01f * v; }

// ---------------------------------------------------------------------------
// Grid barrier (PB blocks, 1/SM). gpu-scope fence is load-bearing.
// ---------------------------------------------------------------------------
__device__ __forceinline__ void gsync() {
    __syncthreads();
    if (threadIdx.x == 0) {
        __threadfence();
        unsigned gen = g_sense;
        if (atomicAdd(&g_count, 1u) == PB - 1u) {
            g_count = 0;
            __threadfence();
            g_sense = gen + 1u;
        } else {
            while (g_sense == gen) { }
        }
    }
    __syncthreads();
}

// ---------------------------------------------------------------------------
// One-hot scan (R12 plain-LDG version — best measured mixed-kernel rate)
// ---------------------------------------------------------------------------
__device__ __forceinline__ void proc_f4(float4 v, int p, int* __restrict__ outp)
{
    if (v.x != 0.0f || v.y != 0.0f || v.z != 0.0f || v.w != 0.0f) {
        int lin = p << 2;
        int row = lin >> 13;
        int col = lin & (N_E - 1);
        if (v.x != 0.0f) outp[col + 0] = row;
        if (v.y != 0.0f) outp[col + 1] = row;
        if (v.z != 0.0f) outp[col + 2] = row;
        if (v.w != 0.0f) outp[col + 3] = row;
    }
}

#define XB_BLOCKS 1024

__device__ void extract_body(const float* __restrict__ mat,
                             int* __restrict__ outp, int xb)
{
    const int PER = N_V * (N_E / 4);
    const int T   = XB_BLOCKS * 256;
    const float4* m4 = reinterpret_cast<const float4*>(mat);
    int base = xb * 256 + threadIdx.x;
    for (int i = base; i < PER; i += 8 * T) {
        float4 v[8];
#pragma unroll
        for (int u = 0; u < 8; u++) v[u] = __ldcs(&m4[i + u * T]);
#pragma unroll
        for (int u = 0; u < 8; u++) proc_f4(v[u], i + u * T, outp);
    }
}

// ---------------------------------------------------------------------------
// Register-tiled GEMM body (rides under the scans): f32x2 inner product.
// C[64,128] = act(A[64,K] @ W[128,K]^T + b); ACT 0=leaky, 1=tanh
// Optional C3 (pitch 384, offset 2*HD: he_out segment 2).
// ---------------------------------------------------------------------------
template<int K, int ACT>
__device__ __forceinline__ void gemm_body(const float* __restrict__ A,
                                          const float* __restrict__ W,
                                          const float* __restrict__ bias,
                                          float* __restrict__ C,
                                          float* __restrict__ C3,
                                          int m0, float* sA, float* sW)
{
    constexpr int BM = 64, BK = 16, BN = 128;
    const int tid = threadIdx.x;
    const int tx  = tid & 15;
    const int ty  = tid >> 4;

    unsigned long long acc[4][4];
#pragma unroll
    for (int i = 0; i < 4; i++)
#pragma unroll
        for (int j = 0; j < 4; j++) acc[i][j] = 0ull;

#pragma unroll
    for (int k0 = 0; k0 < K; k0 += BK) {
        {
            int j0 = tid * 4, m = j0 >> 4, k = j0 & 15;
            float4 a4 = *reinterpret_cast<const float4*>(&A[(m0 + m) * K + k0 + k]);
            sA[(k + 0) * BM + m] = a4.x; sA[(k + 1) * BM + m] = a4.y;
            sA[(k + 2) * BM + m] = a4.z; sA[(k + 3) * BM + m] = a4.w;
        }
        {
            int j0 = tid * 8, n = j0 >> 4, kk = j0 & 15;
            const float* wr = &W[n * K + k0 + kk];
            float4 w0 = *reinterpret_cast<const float4*>(wr);
            float4 w1 = *reinterpret_cast<const float4*>(wr + 4);
            sW[(kk + 0) * BN + n] = w0.x; sW[(kk + 1) * BN + n] = w0.y;
            sW[(kk + 2) * BN + n] = w0.z; sW[(kk + 3) * BN + n] = w0.w;
            sW[(kk + 4) * BN + n] = w1.x; sW[(kk + 5) * BN + n] = w1.y;
            sW[(kk + 6) * BN + n] = w1.z; sW[(kk + 7) * BN + n] = w1.w;
        }
        __syncthreads();
#pragma unroll
        for (int k = 0; k < BK; k++) {
            float a[4];
#pragma unroll
            for (int i = 0; i < 4; i++) a[i] = sA[k * BM + ty * 4 + i];
            ulonglong2 w01 = *reinterpret_cast<const ulonglong2*>(&sW[k * BN + tx * 8]);
            ulonglong2 w23 = *reinterpret_cast<const ulonglong2*>(&sW[k * BN + tx * 8 + 4]);
#pragma unroll
            for (int i = 0; i < 4; i++) {
                unsigned long long aa = pack2(a[i], a[i]);
                fma2(acc[i][0], aa, w01.x);
                fma2(acc[i][1], aa, w01.y);
                fma2(acc[i][2], aa, w23.x);
                fma2(acc[i][3], aa, w23.y);
            }
        }
        __syncthreads();
    }

    float b[8];
#pragma unroll
    for (int j = 0; j < 8; j++) b[j] = bias[tx * 8 + j];

#pragma unroll
    for (int i = 0; i < 4; i++) {
        int m = m0 + ty * 4 + i;
        float out[8];
#pragma unroll
        for (int j = 0; j < 4; j++) {
            float2 v = unpack2(acc[i][j]);
            float u0 = v.x + b[j * 2];
            float u1 = v.y + b[j * 2 + 1];
            if (ACT == 0) { u0 = lrelu(u0); u1 = lrelu(u1); }
            else          { u0 = tanhf(u0); u1 = tanhf(u1); }
            out[j * 2]     = u0;
            out[j * 2 + 1] = u1;
        }
        float4 o0 = make_float4(out[0], out[1], out[2], out[3]);
        float4 o1 = make_float4(out[4], out[5], out[6], out[7]);
        float* crow = &C[m * HD + tx * 8];
        *reinterpret_cast<float4*>(crow)     = o0;
        *reinterpret_cast<float4*>(crow + 4) = o1;
        if (C3) {
            float* c3row = &C3[m * (3 * HD) + 2 * HD + tx * 8];
            *reinterpret_cast<float4*>(c3row)     = o0;
            *reinterpret_cast<float4*>(c3row + 4) = o1;
        }
    }
}

// K1: stage-1 linears + vew1 scan (src)
__global__ __launch_bounds__(256)
void k1_kernel(const float* __restrict__ atom, const float* __restrict__ bond,
               const float* __restrict__ vW1, const float* __restrict__ vb1,
               const float* __restrict__ eW1, const float* __restrict__ eb1,
               const float* __restrict__ vew1,
               float* __restrict__ tmpv, float* __restrict__ tmpe,
               int* __restrict__ src)
{
    __shared__ float sA[16 * 64];
    __shared__ float sW[16 * 128];
    int b = blockIdx.x;
    if (b < 64)
        gemm_body<ATOM_DIM, 0>(atom, vW1, vb1, tmpv, nullptr, b * 64, sA, sW);
    else if (b < 192)
        gemm_body<BOND_DIM, 0>(bond, eW1, eb1, tmpe, nullptr, (b - 64) * 64, sA, sW);
    else
        extract_body(vew1, src, b - 192);
}

// K2: stage-2 linears (tanh; e-branch also writes he_out seg2) + vew2 scan (dst)
__global__ __launch_bounds__(256)
void k2_kernel(const float* __restrict__ tmpv, const float* __restrict__ tmpe,
               const float* __restrict__ vW2, const float* __restrict__ vb2,
               const float* __restrict__ eW2, const float* __restrict__ eb2,
               const float* __restrict__ vew2,
               float* __restrict__ hvA, float* __restrict__ he,
               float* __restrict__ he_out, int* __restrict__ dst)
{
    __shared__ float sA[16 * 64];
    __shared__ float sW[16 * 128];
    int b = blockIdx.x;
    if (b < 64)
        gemm_body<HD, 1>(tmpv, vW2, vb2, hvA, nullptr, b * 64, sA, sW);
    else if (b < 192)
        gemm_body<HD, 1>(tmpe, eW2, eb2, he, he_out, (b - 64) * 64, sA, sW);
    else
        extract_body(vew2, dst, b - 192);
}

// ---------------------------------------------------------------------------
// Persistent kernel — R12 structure; edge gather & he_out software-pipelined,
// dst packed into sList at setup (no dependent dst load in the hot loop).
// ---------------------------------------------------------------------------
__global__ __launch_bounds__(PT, 1)
void persist_kernel(const float* __restrict__ he,
                    float* __restrict__ hvA,
                    const int* __restrict__ src, const int* __restrict__ dst,
                    const float* __restrict__ mlpW, const float* __restrict__ mlpb,
                    float* __restrict__ hv_out, float* __restrict__ he_out)
{
    extern __shared__ float smem[];
    float* sW   = smem;                       // 16384 floats
    float* sAcc = smem + 16384;               // 4096 floats
    int*   sList = (int*)(smem + 20480);      // 32 * MAXE packed (e<<12)|d
    int*   sCnt  = (int*)(smem + 20480 + 32 * MAXE);  // 32 ints

    const int tid  = threadIdx.x;
    const int wid  = tid >> 5;
    const int lane = tid & 31;
    const int bid  = blockIdx.x;
    const int m0   = bid * 32;

    const float4* he4 = reinterpret_cast<const float4*>(he);
    const float4* hv4 = reinterpret_cast<const float4*>(hvA);

    if (tid < 32) sCnt[tid] = 0;
    __syncthreads();
    for (int e = tid; e < N_E; e += PT) {
        int s = __ldg(&src[e]);
        if ((s >> 5) == bid) {
            int rr = s & 31;
            int slot = atomicAdd(&sCnt[rr], 1);
            if (slot < MAXE) sList[rr * MAXE + slot] = (e << 12) | __ldg(&dst[e]);
        }
    }
    {
        float4* sAcc4 = reinterpret_cast<float4*>(sAcc);
        for (int idx = tid; idx < 1024; idx += PT)
            sAcc4[idx] = __ldg(&hv4[m0 * 32 + idx]);
    }
    __syncthreads();

    for (int l = 0; l < N_LAYER; l++) {
        // ---- edge gather, 1-ahead software pipeline ----
#pragma unroll
        for (int q = 0; q < 2; q++) {
            int rr = wid * 2 + q;
            int cnt = sCnt[rr]; if (cnt > MAXE) cnt = MAXE;
            float4 a = *reinterpret_cast<const float4*>(&sAcc[rr * HD + lane * 4]);
            if (cnt > 0) {
                int p = sList[rr * MAXE];
                float4 h = __ldg(&he4[(p >> 12) * 32 + lane]);
                float4 g = __ldg(&hv4[(p & 4095) * 32 + lane]);
                for (int i = 1; i < cnt; i++) {
                    int pn = sList[rr * MAXE + i];
                    float4 hn = __ldg(&he4[(pn >> 12) * 32 + lane]);
                    float4 gn = __ldg(&hv4[(pn & 4095) * 32 + lane]);
                    a.x += fmaxf(h.x + g.x, 0.0f);
                    a.y += fmaxf(h.y + g.y, 0.0f);
                    a.z += fmaxf(h.z + g.z, 0.0f);
                    a.w += fmaxf(h.w + g.w, 0.0f);
                    h = hn; g = gn;
                }
                a.x += fmaxf(h.x + g.x, 0.0f);
                a.y += fmaxf(h.y + g.y, 0.0f);
                a.z += fmaxf(h.z + g.z, 0.0f);
                a.w += fmaxf(h.w + g.w, 0.0f);
            }
            *reinterpret_cast<float4*>(&sAcc[rr * HD + lane * 4]) = a;
        }
        __syncthreads();

        const float* Wl = mlpW + l * (HD * HD);
        const float* bl = mlpb + l * HD;
        {
            int n  = tid & 127;
            int kq = (tid >> 7) * 32;
#pragma unroll
            for (int j = 0; j < 8; j++) {
                float4 w = __ldg(reinterpret_cast<const float4*>(&Wl[n * HD + kq + j * 4]));
                int k = kq + j * 4;
                sW[(k + 0) * HD + n] = w.x;
                sW[(k + 1) * HD + n] = w.y;
                sW[(k + 2) * HD + n] = w.z;
                sW[(k + 3) * HD + n] = w.w;
            }
        }
        __syncthreads();

        if (wid < 8) {
            const int r0 = wid * 4;
            const int c0 = lane * 4;
            unsigned long long acc[4][2];
#pragma unroll
            for (int r = 0; r < 4; r++) { acc[r][0] = 0ull; acc[r][1] = 0ull; }

            for (int k0 = 0; k0 < HD; k0 += 4) {
                float4 av[4];
#pragma unroll
                for (int r = 0; r < 4; r++)
                    av[r] = *reinterpret_cast<const float4*>(&sAcc[(r0 + r) * HD + k0]);
#pragma unroll
                for (int j = 0; j < 4; j++) {
                    ulonglong2 ww = *reinterpret_cast<const ulonglong2*>(&sW[(k0 + j) * HD + c0]);
#pragma unroll
                    for (int r = 0; r < 4; r++) {
                        float a = (j == 0) ? av[r].x : (j == 1) ? av[r].y
                                : (j == 2) ? av[r].z : av[r].w;
                        unsigned long long aa = pack2(a, a);
                        fma2(acc[r][0], aa, ww.x);
                        fma2(acc[r][1], aa, ww.y);
                    }
                }
            }

            float4 b4 = __ldg(reinterpret_cast<const float4*>(&bl[c0]));
            float4 o[4];
#pragma unroll
            for (int r = 0; r < 4; r++) {
                float2 v0 = unpack2(acc[r][0]);
                float2 v1 = unpack2(acc[r][1]);
                o[r] = make_float4(lrelu(v0.x + b4.x), lrelu(v0.y + b4.y),
                                   lrelu(v1.x + b4.z), lrelu(v1.y + b4.w));
            }
            __syncwarp();
#pragma unroll
            for (int r = 0; r < 4; r++) {
                int rr = r0 + r;
                *reinterpret_cast<float4*>(&sAcc[rr * HD + c0]) = o[r];
                *reinterpret_cast<float4*>(&hvA[(m0 + rr) * HD + c0]) = o[r];
                if (l == N_LAYER - 1)
                    *reinterpret_cast<float4*>(&hv_out[(m0 + rr) * HD + c0]) = o[r];
            }
        }
        gsync();
    }

    // ---- he_out segs 0,1 (seg2 by k2), 1-ahead pipeline; exactly 4 iters ----
    float4* out4 = reinterpret_cast<float4*>(he_out);
    {
        int e = bid * 16 + wid;
        int s = __ldg(&src[e]);
        int d = __ldg(&dst[e]);
        float4 v0 = __ldg(&hv4[s * 32 + lane]);
        float4 v1 = __ldg(&hv4[d * 32 + lane]);
#pragma unroll
        for (int k = 0; k < 3; k++) {
            int e2 = e + NWARP_P;
            int s2 = __ldg(&src[e2]);
            int d2 = __ldg(&dst[e2]);
            float4 w0 = __ldg(&hv4[s2 * 32 + lane]);
            float4 w1 = __ldg(&hv4[d2 * 32 + lane]);
            out4[e * 96 + lane]      = v0;
            out4[e * 96 + 32 + lane] = v1;
            e = e2; v0 = w0; v1 = w1;
        }
        out4[e * 96 + lane]      = v0;
        out4[e * 96 + 32 + lane] = v1;
    }
}

// ---------------------------------------------------------------------------
// Launcher
// ---------------------------------------------------------------------------
extern "C" void kernel_launch(void* const* d_in, const int* in_sizes, int n_in,
                              void* d_out, int out_size)
{
    const float* atom = (const float*)d_in[0];
    const float* bond = (const float*)d_in[1];
    const float* vew1 = (const float*)d_in[2];
    const float* vew2 = (const float*)d_in[3];
    const float* vW1  = (const float*)d_in[4];
    const float* vb1  = (const float*)d_in[5];
    const float* vW2  = (const float*)d_in[6];
    const float* vb2  = (const float*)d_in[7];
    const float* eW1  = (const float*)d_in[8];
    const float* eb1  = (const float*)d_in[9];
    const float* eW2  = (const float*)d_in[10];
    const float* eb2  = (const float*)d_in[11];
    const float* mlpW = (const float*)d_in[12];
    const float* mlpb = (const float*)d_in[13];

    float *tmpv, *tmpe, *he, *hvA;
    int *src, *dst;
    cudaGetSymbolAddress((void**)&tmpv, g_tmpv);
    cudaGetSymbolAddress((void**)&tmpe, g_tmpe);
    cudaGetSymbolAddress((void**)&he,   g_he);
    cudaGetSymbolAddress((void**)&hvA,  g_hvA);
    cudaGetSymbolAddress((void**)&src,  g_src);
    cudaGetSymbolAddress((void**)&dst,  g_dst);

    float* hv_out = (float*)d_out;
    float* he_out = (float*)d_out + (long long)N_V * HD;

    const int PER_SMEM = (16384 + 4096) * 4 + (32 * MAXE + 32) * 4;
    cudaFuncSetAttribute(persist_kernel,
                         cudaFuncAttributeMaxDynamicSharedMemorySize, PER_SMEM);

    k1_kernel<<<192 + XB_BLOCKS, 256>>>(atom, bond, vW1, vb1, eW1, eb1,
                                        vew1, tmpv, tmpe, src);
    k2_kernel<<<192 + XB_BLOCKS, 256>>>(tmpv, tmpe, vW2, vb2, eW2, eb2,
                                        vew2, hvA, he, he_out, dst);
    persist_kernel<<<PB, PT, PER_SMEM>>>(he, hvA, src, dst,
                                         mlpW, mlpb, hv_out, he_out);
}